// round 16
// baseline (speedup 1.0000x reference)
#include <cuda_runtime.h>
#include <cuda_fp16.h>
#include <cstdint>

// Problem constants
#define BATCH 256
#define DIM   512
#define TT    96
#define NTOK  (BATCH * TT)        // 24576
#define KEMB  8192
#define NELEM (BATCH * DIM * TT)  // 12582912
#define NCHK  (KEMB / 128)        // 64 column chunks
#define NTILES (NCHK * (NTOK / 128))  // 12288
#define PGRID 296                 // persistent CTAs (2 per SM on 148 SMs)

// Tier-1 GEMM geometry: CTA 128x128 tile, 8 warps, warp tile 64x32,
// XOR-swizzled 128B smem rows, 3-slot stage ring spanning tile boundaries.
#define BM 128
#define BN 128
#define ROWB 128
#define A_REGION (BM * ROWB)          // 16384
#define STG_BYTES ((BM + BN) * ROWB)  // 32768
#define NSTG 3
#define DYN_SMEM (NSTG * STG_BYTES)   // 98304
#define NKIT_I8 4                     // 512 int8 / 128 per stage

#define MARGIN1 3.2f              // int8 certification margin (~6 sigma)
#define FINF __int_as_float(0x7f800000)
#define NEXACT_CTAS 2048

// Scratch (static device allocations are allowed)
__device__ signed char g_Ax8[(size_t)NTOK * DIM];  // int8 tokens
__device__ signed char g_Be8[(size_t)KEMB * DIM];  // int8 embeddings
__device__ float  g_invx[NTOK];                // per-row x scale (max/127)
__device__ float  g_inve[KEMB];                // per-row e scale
__device__ float  g_esq[KEMB];
__device__ unsigned long long g_best[NTOK];    // packed (mapped_score<<32)|idx
__device__ unsigned int g_best2[NTOK];         // mapped second-best score
__device__ unsigned long long g_blk1[(size_t)NCHK * NTOK];  // per (chunk,row) min1
__device__ unsigned int g_blk2[(size_t)NCHK * NTOK];        // per (chunk,row) min2
__device__ float g_thr[NTOK];                  // exact-rescore threshold
__device__ int g_nfall;
__device__ int g_fall[NTOK];
__device__ double g_loss_acc;

// ---------------------------------------------------------------------------
__device__ __forceinline__ unsigned map_u(float s) {
    unsigned u = __float_as_uint(s);
    return (u & 0x80000000u) ? ~u : (u | 0x80000000u);  // order-preserving
}
__device__ __forceinline__ unsigned long long pack_score(float s, int idx) {
    return ((unsigned long long)map_u(s) << 32) | (unsigned)idx;
}
__device__ __forceinline__ float unmap_score(unsigned u) {
    unsigned v = (u & 0x80000000u) ? (u & 0x7FFFFFFFu) : ~u;
    return __uint_as_float(v);
}
__device__ __forceinline__ void cp_async16(uint32_t smem, const void* gmem) {
    asm volatile("cp.async.cg.shared.global [%0], [%1], 16;\n" ::"r"(smem), "l"(gmem));
}
// BRANCHLESS (s1,i1,s2) update (r14-proven).
__device__ __forceinline__ void fupd(float& s1, int& i1, float& s2, float sc, int k) {
    bool p = sc < s1;
    float ns2 = p ? s1 : fminf(s2, sc);
    i1 = p ? k : i1;
    s1 = p ? sc : s1;
    s2 = ns2;
}
__device__ __forceinline__ void fmerge(float& s1, int& i1, float& s2, int o) {
    float os1 = __shfl_xor_sync(0xffffffffu, s1, o);
    int   oi1 = __shfl_xor_sync(0xffffffffu, i1, o);
    float os2 = __shfl_xor_sync(0xffffffffu, s2, o);
    if (os1 < s1 || (os1 == s1 && oi1 < i1)) {
        s2 = fminf(s1, os2); s1 = os1; i1 = oi1;
    } else {
        s2 = fminf(s2, os1);
    }
}

// ---------------------------------------------------------------------------
__global__ void k_init() {
    int i = blockIdx.x * blockDim.x + threadIdx.x;
    if (i < NTOK) { g_best[i] = 0xFFFFFFFFFFFFFFFFULL; g_best2[i] = 0xFFFFFFFFu; }
    if (i == 0) { g_loss_acc = 0.0; g_nfall = 0; }
}

// x [B, D, T] -> g_Ax8 int8 (per-row symmetric scale) + g_invx.
__global__ void k_prep_x(const float* __restrict__ x) {
    extern __shared__ float tile[];          // [512][33]
    int b  = blockIdx.y;
    int t0 = blockIdx.x * 32;
    int tid = threadIdx.x;
#pragma unroll 4
    for (int it = 0; it < 64; it++) {
        int d = it * 8 + (tid >> 5);
        int t = tid & 31;
        tile[d * 33 + t] = x[((size_t)b * DIM + d) * TT + t0 + t];
    }
    __syncthreads();
    int lane = tid & 31;
#pragma unroll
    for (int pass = 0; pass < 4; pass++) {
        int t = pass * 8 + (tid >> 5);
        size_t row = (size_t)b * TT + t0 + t;
        float v[16], m = 0.f;
#pragma unroll
        for (int i = 0; i < 16; i++) {
            v[i] = tile[(lane + i * 32) * 33 + t];
            m = fmaxf(m, fabsf(v[i]));
        }
#pragma unroll
        for (int o = 16; o; o >>= 1) m = fmaxf(m, __shfl_xor_sync(~0u, m, o));
        m = fmaxf(m, 1e-6f);
        float s = 127.f / m;
#pragma unroll
        for (int i = 0; i < 16; i++)
            g_Ax8[row * DIM + lane + i * 32] = (signed char)__float2int_rn(v[i] * s);
        if (lane == 0) g_invx[row] = m * (1.f / 127.f);
    }
}

// E [K, D] -> g_Be8 int8 + g_inve + g_esq. One warp per row.
__global__ void k_prep_e(const float* __restrict__ E) {
    int warp = (blockIdx.x * blockDim.x + threadIdx.x) >> 5;
    int lane = threadIdx.x & 31;
    if (warp >= KEMB) return;
    const float4* row = reinterpret_cast<const float4*>(E + (size_t)warp * DIM);
    float4 v[4];
    float s = 0.f, m = 0.f;
#pragma unroll
    for (int i = 0; i < 4; i++) {
        v[i] = row[lane + i * 32];
        s += v[i].x * v[i].x + v[i].y * v[i].y + v[i].z * v[i].z + v[i].w * v[i].w;
        m = fmaxf(m, fmaxf(fmaxf(fabsf(v[i].x), fabsf(v[i].y)),
                           fmaxf(fabsf(v[i].z), fabsf(v[i].w))));
    }
#pragma unroll
    for (int o = 16; o; o >>= 1) {
        s += __shfl_xor_sync(~0u, s, o);
        m = fmaxf(m, __shfl_xor_sync(~0u, m, o));
    }
    m = fmaxf(m, 1e-6f);
    float q = 127.f / m;
    char4* dst8 = reinterpret_cast<char4*>(g_Be8 + (size_t)warp * DIM);
#pragma unroll
    for (int i = 0; i < 4; i++) {
        char4 c;
        c.x = (signed char)__float2int_rn(v[i].x * q);
        c.y = (signed char)__float2int_rn(v[i].y * q);
        c.z = (signed char)__float2int_rn(v[i].z * q);
        c.w = (signed char)__float2int_rn(v[i].w * q);
        dst8[lane + i * 32] = c;
    }
    if (lane == 0) { g_esq[warp] = s; g_inve[warp] = m * (1.f / 127.f); }
}

// ---------------------------------------------------------------------------
__device__ __forceinline__ void epi_commit(unsigned long long* sb1, unsigned* sb2,
                                           int r, float s1, int i1, float s2) {
    unsigned long long p1 = pack_score(s1, i1);
    unsigned long long old = atomicMin(&sb1[r], p1);
    unsigned long long disp = (old > p1) ? old : p1;
    atomicMin(&sb2[r], min(map_u(s2), (unsigned)(disp >> 32)));
}

// TIER 1: PERSISTENT int8 distance GEMM. 296 CTAs loop over 12288 tiles
// (tile>>6 = row-tile, tile&63 = 128-col chunk). Continuous 3-slot cp.async
// pipeline across tile boundaries: compute pos p, p+1 in flight, p+2 issued.
__global__ __launch_bounds__(256, 2) void k_gemm_i8() {
    extern __shared__ char dyn[];
    __shared__ unsigned long long sb1[BM];
    __shared__ unsigned int sb2[BM];
    __shared__ float s_esq[BN], s_inve[BN], s_invx[BM];

    const int tid  = threadIdx.x;
    const int lane = tid & 31;
    const int wid  = tid >> 5;
    const int warprow = wid >> 2;
    const int warpcol = wid & 3;
    const uint32_t dbase = (uint32_t)__cvta_generic_to_shared(dyn);

    // loader mapping
    const int rb = tid >> 3;
    const int cs = tid & 7;
    const int xm = rb & 7;
    const uint32_t dst0 = (uint32_t)(rb * ROWB + ((cs ^ xm) << 4));

    // ldmatrix per-lane constants
    const int a_r = lane & 15;
    const int a_hi = lane >> 4;
    const int a_m = a_r & 7;
    const int b_g   = lane & 7;
    const int b_sel = lane >> 3;
    const int b_roff = ((b_sel & 2) ? 8 : 0) + b_g;
    const int b_lo  = b_sel & 1;
    uint32_t a_row[4], b_row[2];
#pragma unroll
    for (int mf = 0; mf < 4; mf++)
        a_row[mf] = (uint32_t)((warprow * 64 + mf * 16 + a_r) * ROWB);
#pragma unroll
    for (int nh = 0; nh < 2; nh++)
        b_row[nh] = (uint32_t)(A_REGION + (warpcol * 32 + nh * 16 + b_roff) * ROWB);
    uint32_t a_xk[4], b_xk[4];
#pragma unroll
    for (int kk = 0; kk < 4; kk++) {
        a_xk[kk] = (uint32_t)(((kk * 2 + a_hi) ^ a_m) << 4);
        b_xk[kk] = (uint32_t)(((kk * 2 + b_lo) ^ b_g) << 4);
    }

    // cross-tile load pipeline state
    int lt = blockIdx.x;   // tile of next load position
    int lkt = 0;           // kt of next load position
    auto issue_load = [&](int slot) {
        if (lt < NTILES) {
            int lrow0 = (lt >> 6) * BM;
            int ln0   = (lt & 63) * BN;
            const signed char* a =
                g_Ax8 + (size_t)(lrow0 + rb) * DIM + cs * 16 + lkt * 128;
            const signed char* b =
                g_Be8 + (size_t)(ln0 + rb) * DIM + cs * 16 + lkt * 128;
            uint32_t sa = dbase + slot * STG_BYTES + dst0;
#pragma unroll
            for (int i = 0; i < 4; i++)
                cp_async16(sa + i * (32 * ROWB), a + (size_t)(32 * i) * DIM);
#pragma unroll
            for (int i = 0; i < 4; i++)
                cp_async16(sa + A_REGION + i * (32 * ROWB),
                           b + (size_t)(32 * i) * DIM);
        }
        asm volatile("cp.async.commit_group;\n");   // always commit (count sync)
        if (++lkt == NKIT_I8) { lkt = 0; lt += gridDim.x; }
    };

    int pos = 0;           // global compute position counter (slot = pos % 3)
    issue_load(0);
    issue_load(1);

    for (int tile = blockIdx.x; tile < NTILES; tile += gridDim.x) {
        const int row0  = (tile >> 6) * BM;
        const int chunk = tile & 63;
        const int n0    = chunk * BN;

        // per-tile smem prep (published by the kt=0 barrier below)
        for (int i = tid; i < BM; i += 256) {
            sb1[i] = 0xFFFFFFFFFFFFFFFFULL;
            sb2[i] = 0xFFFFFFFFu;
        }
        if (tid < 128) {
            s_esq[tid]  = g_esq[n0 + tid];
            s_inve[tid] = g_inve[n0 + tid];
            s_invx[tid] = g_invx[row0 + tid];
        }

        int acc[16][4];
#pragma unroll
        for (int i = 0; i < 16; i++)
#pragma unroll
            for (int c = 0; c < 4; c++) acc[i][c] = 0;

#pragma unroll
        for (int kt = 0; kt < NKIT_I8; kt++) {
            asm volatile("cp.async.wait_group %0;\n" ::"n"(1));  // pos arrived
            // Barrier: publishes stage pos + sb/s_* prep, and proves all warps
            // finished compute pos-1, freeing slot (pos+2)%3 for overwrite.
            __syncthreads();
            issue_load((pos + 2) % 3);
            const uint32_t sS = dbase + (pos % 3) * STG_BYTES;
            pos++;

#pragma unroll
            for (int kk = 0; kk < 4; kk++) {
                uint32_t a_reg[4][4];
                uint32_t b_reg[2][4];
#pragma unroll
                for (int mf = 0; mf < 4; mf++) {
                    asm volatile(
                        "ldmatrix.sync.aligned.m8n8.x4.shared.b16 {%0,%1,%2,%3}, [%4];\n"
                        : "=r"(a_reg[mf][0]), "=r"(a_reg[mf][1]),
                          "=r"(a_reg[mf][2]), "=r"(a_reg[mf][3])
                        : "r"(sS + a_row[mf] + a_xk[kk]));
                }
#pragma unroll
                for (int nh = 0; nh < 2; nh++) {
                    asm volatile(
                        "ldmatrix.sync.aligned.m8n8.x4.shared.b16 {%0,%1,%2,%3}, [%4];\n"
                        : "=r"(b_reg[nh][0]), "=r"(b_reg[nh][1]),
                          "=r"(b_reg[nh][2]), "=r"(b_reg[nh][3])
                        : "r"(sS + b_row[nh] + b_xk[kk]));
                }
#pragma unroll
                for (int mf = 0; mf < 4; mf++)
#pragma unroll
                    for (int nf = 0; nf < 4; nf++) {
                        const uint32_t* b2p = &b_reg[nf >> 1][(nf & 1) * 2];
                        asm volatile(
                            "mma.sync.aligned.m16n8k32.row.col.s32.s8.s8.s32 "
                            "{%0,%1,%2,%3}, {%4,%5,%6,%7}, {%8,%9}, {%0,%1,%2,%3};\n"
                            : "+r"(acc[mf * 4 + nf][0]), "+r"(acc[mf * 4 + nf][1]),
                              "+r"(acc[mf * 4 + nf][2]), "+r"(acc[mf * 4 + nf][3])
                            : "r"(a_reg[mf][0]), "r"(a_reg[mf][1]),
                              "r"(a_reg[mf][2]), "r"(a_reg[mf][3]),
                              "r"(b2p[0]), "r"(b2p[1]));
                    }
            }
        }

        // Branchless float epilogue: score = ||e||^2 - (2*invx*inve)*acc.
#pragma unroll
        for (int mf = 0; mf < 4; mf++) {
            int r0 = warprow * 64 + mf * 16 + (lane >> 2);
            float w0 = 2.f * s_invx[r0], w1 = 2.f * s_invx[r0 + 8];
            float s1a = FINF, s2a = FINF, s1b = FINF, s2b = FINF;
            int i1a = 0, i1b = 0;
#pragma unroll
            for (int nf = 0; nf < 4; nf++) {
                int kl = warpcol * 32 + nf * 8 + 2 * (lane & 3);
                int k = n0 + kl;
                float e0 = s_esq[kl], e1 = s_esq[kl + 1];
                float v0 = s_inve[kl], v1 = s_inve[kl + 1];
                fupd(s1a, i1a, s2a, fmaf(-w0 * v0, (float)acc[mf * 4 + nf][0], e0), k);
                fupd(s1a, i1a, s2a, fmaf(-w0 * v1, (float)acc[mf * 4 + nf][1], e1), k + 1);
                fupd(s1b, i1b, s2b, fmaf(-w1 * v0, (float)acc[mf * 4 + nf][2], e0), k);
                fupd(s1b, i1b, s2b, fmaf(-w1 * v1, (float)acc[mf * 4 + nf][3], e1), k + 1);
            }
#pragma unroll
            for (int o = 1; o < 4; o <<= 1) {
                fmerge(s1a, i1a, s2a, o);
                fmerge(s1b, i1b, s2b, o);
            }
            if ((lane & 3) == 0) {
                epi_commit(sb1, sb2, r0, s1a, i1a, s2a);
                epi_commit(sb1, sb2, r0 + 8, s1b, i1b, s2b);
            }
        }
        __syncthreads();   // all epilogue atomics done before merge reads
        for (int i = tid; i < BM; i += 256) {
            unsigned long long v1 = sb1[i];
            g_blk1[(size_t)chunk * NTOK + row0 + i] = v1;
            g_blk2[(size_t)chunk * NTOK + row0 + i] = sb2[i];
            unsigned long long old = atomicMin(&g_best[row0 + i], v1);
            unsigned long long disp = (old > v1) ? old : v1;
            atomicMin(&g_best2[row0 + i], min(sb2[i], (unsigned)(disp >> 32)));
        }
        __syncthreads();   // merge reads done before next tile's sb reset
    }
}

// ---------------------------------------------------------------------------
// Flag uncertain rows (gap < MARGIN1); record threshold; reset their mins.
__global__ void k_select1() {
    int i = blockIdx.x * blockDim.x + threadIdx.x;
    if (i >= NTOK) return;
    float s1 = unmap_score((unsigned)(g_best[i] >> 32));
    float s2 = unmap_score(g_best2[i]);
    if (s2 - s1 < MARGIN1) {
        int p = atomicAdd(&g_nfall, 1);
        g_fall[p] = i;
        g_thr[i] = s1 + MARGIN1;
        g_best[i] = 0xFFFFFFFFFFFFFFFFULL;
    }
}

// ---------------------------------------------------------------------------
// Candidate-based exact fp32 resolution (r15-proven). One CTA per flagged row.
__global__ __launch_bounds__(128) void k_exact(const float* __restrict__ E,
                                               const float* __restrict__ x) {
    __shared__ __align__(16) float xs[DIM];
    __shared__ int dir[NCHK];
    __shared__ int deep[NCHK];
    __shared__ int nd, nz;
    __shared__ unsigned long long best;

    const int tid = threadIdx.x;
    const int wid = tid >> 5;
    const int lane = tid & 31;
    const int n = g_nfall;

    for (int r = blockIdx.x; r < n; r += gridDim.x) {
        const int row = g_fall[r];
        if (tid == 0) { nd = 0; nz = 0; best = 0xFFFFFFFFFFFFFFFFULL; }
        __syncthreads();
        const float T = g_thr[row];
        {
            int b = row / TT, t = row % TT;
            for (int d = tid; d < DIM; d += 128)
                xs[d] = x[((size_t)b * DIM + d) * TT + t];
        }
        if (tid < NCHK) {
            unsigned long long m1 = g_blk1[(size_t)tid * NTOK + row];
            float c1 = unmap_score((unsigned)(m1 >> 32));
            float c2 = unmap_score(g_blk2[(size_t)tid * NTOK + row]);
            if (c2 <= T)       deep[atomicAdd(&nz, 1)] = tid;
            else if (c1 <= T)  dir[atomicAdd(&nd, 1)] = (int)(m1 & 0xFFFFFFFFu);
        }
        __syncthreads();

        for (int j = wid; j < nd; j += 4) {
            int k = dir[j];
            const float4* e4 = reinterpret_cast<const float4*>(E + (size_t)k * DIM);
            const float4* x4 = reinterpret_cast<const float4*>(xs);
            float s = 0.f;
#pragma unroll
            for (int i = 0; i < 4; i++) {
                float4 ev = e4[lane + i * 32], xv = x4[lane + i * 32];
                s += ev.x * xv.x + ev.y * xv.y + ev.z * xv.z + ev.w * xv.w;
            }
#pragma unroll
            for (int o = 16; o; o >>= 1) s += __shfl_xor_sync(~0u, s, o);
            if (lane == 0)
                atomicMin(&best, pack_score(g_esq[k] - 2.f * s, k));
        }
        for (int z = 0; z < nz; z++) {
            int kbase = deep[z] * BN;
            for (int j = wid; j < BN; j += 4) {
                int k = kbase + j;
                const float4* e4 = reinterpret_cast<const float4*>(E + (size_t)k * DIM);
                const float4* x4 = reinterpret_cast<const float4*>(xs);
                float s = 0.f;
#pragma unroll
                for (int i = 0; i < 4; i++) {
                    float4 ev = e4[lane + i * 32], xv = x4[lane + i * 32];
                    s += ev.x * xv.x + ev.y * xv.y + ev.z * xv.z + ev.w * xv.w;
                }
#pragma unroll
                for (int o = 16; o; o >>= 1) s += __shfl_xor_sync(~0u, s, o);
                if (lane == 0)
                    atomicMin(&best, pack_score(g_esq[k] - 2.f * s, k));
            }
        }
        __syncthreads();
        if (tid == 0) atomicMin(&g_best[row], best);
        __syncthreads();
    }
}

// ---------------------------------------------------------------------------
// Gather quantized = E[idx], permute back to [B, D, T], fused loss accum.
__global__ void k_output(const float* __restrict__ E, const float* __restrict__ x,
                         float* __restrict__ out) {
    __shared__ float s[TT][68];
    __shared__ int sidx[TT];
    __shared__ float wred[8];
    int b  = blockIdx.y;
    int d0 = blockIdx.x * 64;
    int tid = threadIdx.x;
    if (tid < TT) sidx[tid] = (int)(g_best[(size_t)b * TT + tid] & 0xFFFFFFFFu);
    __syncthreads();
    for (int i = tid; i < TT * 16; i += 256) {
        int t = i >> 4, c = (i & 15) * 4;
        float4 v = *reinterpret_cast<const float4*>(
            E + (size_t)sidx[t] * DIM + d0 + c);
        s[t][c] = v.x; s[t][c + 1] = v.y; s[t][c + 2] = v.z; s[t][c + 3] = v.w;
    }
    __syncthreads();
    float fsum = 0.f;
    for (int i = tid; i < 64 * TT; i += 256) {
        int dd = i / TT, t = i % TT;
        float e = s[t][dd];
        size_t off = ((size_t)b * DIM + d0 + dd) * TT + t;
        float df = e - x[off];
        fsum += df * df;
        out[off] = e;
    }
#pragma unroll
    for (int o = 16; o; o >>= 1) fsum += __shfl_xor_sync(~0u, fsum, o);
    if ((tid & 31) == 0) wred[tid >> 5] = fsum;
    __syncthreads();
    if (tid == 0) {
        float t = 0.f;
#pragma unroll
        for (int i = 0; i < 8; i++) t += wred[i];
        atomicAdd(&g_loss_acc, (double)t);
    }
}

__global__ void k_finalize(float* out, int out_size) {
    if (out_size > NELEM)
        out[NELEM] = (float)(1.25 * g_loss_acc / (double)((size_t)NTOK * DIM));
}

// ---------------------------------------------------------------------------
extern "C" void kernel_launch(void* const* d_in, const int* in_sizes, int n_in,
                              void* d_out, int out_size) {
    const float* x = (const float*)d_in[0];
    const float* E = (const float*)d_in[1];
    float* out = (float*)d_out;

    static int configured = 0;
    if (!configured) {
        cudaFuncSetAttribute(k_gemm_i8,
                             cudaFuncAttributeMaxDynamicSharedMemorySize, DYN_SMEM);
        cudaFuncSetAttribute(k_prep_x,
                             cudaFuncAttributeMaxDynamicSharedMemorySize,
                             512 * 33 * (int)sizeof(float));
        configured = 1;
    }

    k_init<<<(NTOK + 255) / 256, 256>>>();
    k_prep_x<<<dim3(TT / 32, BATCH), 256, 512 * 33 * sizeof(float)>>>(x);
    k_prep_e<<<KEMB / 8, 256>>>(E);
    k_gemm_i8<<<PGRID, 256, DYN_SMEM>>>();
    k_select1<<<(NTOK + 255) / 256, 256>>>();
    k_exact<<<NEXACT_CTAS, 128>>>(E, x);
    k_output<<<dim3(DIM / 64, BATCH), 256>>>(E, x, out);
    k_finalize<<<1, 1>>>(out, out_size);
}

// round 17
// speedup vs baseline: 1.1187x; 1.1187x over previous
#include <cuda_runtime.h>
#include <cuda_fp16.h>
#include <cstdint>

// Problem constants
#define BATCH 256
#define DIM   512
#define TT    96
#define NTOK  (BATCH * TT)        // 24576
#define KEMB  8192
#define NELEM (BATCH * DIM * TT)  // 12582912
#define NCHK  (KEMB / 128)        // 64 column chunks

// Tier-1 GEMM geometry (r15-proven): CTA 128x128, 8 warps, warp tile 64x32,
// XOR-swizzled 128B smem rows, 3 stages, one barrier per k-iteration.
#define BM 128
#define BN 128
#define ROWB 128
#define A_REGION (BM * ROWB)          // 16384
#define STG_BYTES ((BM + BN) * ROWB)  // 32768
#define NSTG 3
#define DYN_SMEM (NSTG * STG_BYTES)   // 98304
#define NKIT_I8 4                     // 512 int8 / 128 per stage

#define MARGIN1 3.2f              // int8 certification margin (~6 sigma)
#define FINF __int_as_float(0x7f800000)
#define NEXACT_CTAS 2048

// Scratch (static device allocations are allowed)
__device__ signed char g_Ax8[(size_t)NTOK * DIM];  // int8 tokens
__device__ signed char g_Be8[(size_t)KEMB * DIM];  // int8 embeddings
__device__ float  g_invx[NTOK];                // per-row x scale (max/127)
__device__ float  g_inve[KEMB];                // per-row e scale
__device__ float  g_esq[KEMB];
__device__ unsigned long long g_best[NTOK];    // packed (mapped_score<<32)|idx
__device__ unsigned long long g_blk1[(size_t)NCHK * NTOK];  // per (chunk,row) min1
__device__ unsigned int g_blk2[(size_t)NCHK * NTOK];        // per (chunk,row) min2
__device__ float g_thr[NTOK];                  // exact-rescore threshold
__device__ int g_nfall;
__device__ int g_fall[NTOK];
__device__ double g_loss_acc;

// ---------------------------------------------------------------------------
__device__ __forceinline__ unsigned map_u(float s) {
    unsigned u = __float_as_uint(s);
    return (u & 0x80000000u) ? ~u : (u | 0x80000000u);  // order-preserving
}
__device__ __forceinline__ unsigned long long pack_score(float s, int idx) {
    return ((unsigned long long)map_u(s) << 32) | (unsigned)idx;
}
__device__ __forceinline__ float unmap_score(unsigned u) {
    unsigned v = (u & 0x80000000u) ? (u & 0x7FFFFFFFu) : ~u;
    return __uint_as_float(v);
}
__device__ __forceinline__ void cp_async16(uint32_t smem, const void* gmem) {
    asm volatile("cp.async.cg.shared.global [%0], [%1], 16;\n" ::"r"(smem), "l"(gmem));
}
// BRANCHLESS (s1,i1,s2) update (r14-proven).
__device__ __forceinline__ void fupd(float& s1, int& i1, float& s2, float sc, int k) {
    bool p = sc < s1;
    float ns2 = p ? s1 : fminf(s2, sc);
    i1 = p ? k : i1;
    s1 = p ? sc : s1;
    s2 = ns2;
}
__device__ __forceinline__ void fmerge(float& s1, int& i1, float& s2, int o) {
    float os1 = __shfl_xor_sync(0xffffffffu, s1, o);
    int   oi1 = __shfl_xor_sync(0xffffffffu, i1, o);
    float os2 = __shfl_xor_sync(0xffffffffu, s2, o);
    if (os1 < s1 || (os1 == s1 && oi1 < i1)) {
        s2 = fminf(s1, os2); s1 = os1; i1 = oi1;
    } else {
        s2 = fminf(s2, os1);
    }
}

// ---------------------------------------------------------------------------
__global__ void k_init() {
    if (blockIdx.x == 0 && threadIdx.x == 0) { g_loss_acc = 0.0; g_nfall = 0; }
}

// x [B, D, T] -> g_Ax8 int8 (per-row symmetric scale) + g_invx.
__global__ void k_prep_x(const float* __restrict__ x) {
    extern __shared__ float tile[];          // [512][33]
    int b  = blockIdx.y;
    int t0 = blockIdx.x * 32;
    int tid = threadIdx.x;
#pragma unroll 4
    for (int it = 0; it < 64; it++) {
        int d = it * 8 + (tid >> 5);
        int t = tid & 31;
        tile[d * 33 + t] = x[((size_t)b * DIM + d) * TT + t0 + t];
    }
    __syncthreads();
    int lane = tid & 31;
#pragma unroll
    for (int pass = 0; pass < 4; pass++) {
        int t = pass * 8 + (tid >> 5);
        size_t row = (size_t)b * TT + t0 + t;
        float v[16], m = 0.f;
#pragma unroll
        for (int i = 0; i < 16; i++) {
            v[i] = tile[(lane + i * 32) * 33 + t];
            m = fmaxf(m, fabsf(v[i]));
        }
#pragma unroll
        for (int o = 16; o; o >>= 1) m = fmaxf(m, __shfl_xor_sync(~0u, m, o));
        m = fmaxf(m, 1e-6f);
        float s = 127.f / m;
#pragma unroll
        for (int i = 0; i < 16; i++)
            g_Ax8[row * DIM + lane + i * 32] = (signed char)__float2int_rn(v[i] * s);
        if (lane == 0) g_invx[row] = m * (1.f / 127.f);
    }
}

// E [K, D] -> g_Be8 int8 + g_inve + g_esq. One warp per row.
__global__ void k_prep_e(const float* __restrict__ E) {
    int warp = (blockIdx.x * blockDim.x + threadIdx.x) >> 5;
    int lane = threadIdx.x & 31;
    if (warp >= KEMB) return;
    const float4* row = reinterpret_cast<const float4*>(E + (size_t)warp * DIM);
    float4 v[4];
    float s = 0.f, m = 0.f;
#pragma unroll
    for (int i = 0; i < 4; i++) {
        v[i] = row[lane + i * 32];
        s += v[i].x * v[i].x + v[i].y * v[i].y + v[i].z * v[i].z + v[i].w * v[i].w;
        m = fmaxf(m, fmaxf(fmaxf(fabsf(v[i].x), fabsf(v[i].y)),
                           fmaxf(fabsf(v[i].z), fabsf(v[i].w))));
    }
#pragma unroll
    for (int o = 16; o; o >>= 1) {
        s += __shfl_xor_sync(~0u, s, o);
        m = fmaxf(m, __shfl_xor_sync(~0u, m, o));
    }
    m = fmaxf(m, 1e-6f);
    float q = 127.f / m;
    char4* dst8 = reinterpret_cast<char4*>(g_Be8 + (size_t)warp * DIM);
#pragma unroll
    for (int i = 0; i < 4; i++) {
        char4 c;
        c.x = (signed char)__float2int_rn(v[i].x * q);
        c.y = (signed char)__float2int_rn(v[i].y * q);
        c.z = (signed char)__float2int_rn(v[i].z * q);
        c.w = (signed char)__float2int_rn(v[i].w * q);
        dst8[lane + i * 32] = c;
    }
    if (lane == 0) { g_esq[warp] = s; g_inve[warp] = m * (1.f / 127.f); }
}

// ---------------------------------------------------------------------------
__device__ __forceinline__ void epi_commit(unsigned long long* sb1, unsigned* sb2,
                                           int r, float s1, int i1, float s2) {
    unsigned long long p1 = pack_score(s1, i1);
    unsigned long long old = atomicMin(&sb1[r], p1);
    unsigned long long disp = (old > p1) ? old : p1;
    atomicMin(&sb2[r], min(map_u(s2), (unsigned)(disp >> 32)));
}

// TIER 1: int8 distance GEMM (mma.s8 m16n8k32) + branchless (min1,min2).
// Writes per-(chunk,row) minima ONLY (plain coalesced stores; no global
// atomics) — the cross-chunk reduction happens in k_select1.
__global__ __launch_bounds__(256, 2) void k_gemm_i8() {
    extern __shared__ char dyn[];
    __shared__ unsigned long long sb1[BM];
    __shared__ unsigned int sb2[BM];
    __shared__ float s_esq[BN], s_inve[BN], s_invx[BM];

    const int tid  = threadIdx.x;
    const int lane = tid & 31;
    const int wid  = tid >> 5;
    const int warprow = wid >> 2;
    const int warpcol = wid & 3;
    const int row0 = blockIdx.y * BM;
    const int n0   = blockIdx.x * BN;
    const uint32_t dbase = (uint32_t)__cvta_generic_to_shared(dyn);

    for (int i = tid; i < BM; i += 256) {
        sb1[i] = 0xFFFFFFFFFFFFFFFFULL;
        sb2[i] = 0xFFFFFFFFu;
    }
    if (tid < 128) {
        s_esq[tid]  = g_esq[n0 + tid];
        s_inve[tid] = g_inve[n0 + tid];
        s_invx[tid] = g_invx[row0 + tid];
    }

    const int rb = tid >> 3;
    const int cs = tid & 7;
    const int xm = rb & 7;
    const signed char* gA = g_Ax8 + (size_t)(row0 + rb) * DIM + cs * 16;
    const signed char* gB = g_Be8 + (size_t)(n0 + rb) * DIM + cs * 16;
    const uint32_t dst0 = (uint32_t)(rb * ROWB + ((cs ^ xm) << 4));

    auto load_stage = [&](int kt, int stg) {
        uint32_t sa = dbase + stg * STG_BYTES + dst0;
        const signed char* a = gA + kt * 128;
        const signed char* b = gB + kt * 128;
#pragma unroll
        for (int i = 0; i < 4; i++)
            cp_async16(sa + i * (32 * ROWB), a + (size_t)(32 * i) * DIM);
#pragma unroll
        for (int i = 0; i < 4; i++)
            cp_async16(sa + A_REGION + i * (32 * ROWB), b + (size_t)(32 * i) * DIM);
    };

    int acc[16][4];
#pragma unroll
    for (int i = 0; i < 16; i++)
#pragma unroll
        for (int c = 0; c < 4; c++) acc[i][c] = 0;

    const int a_r = lane & 15;
    const int a_hi = lane >> 4;
    const int a_m = a_r & 7;
    const int b_g   = lane & 7;
    const int b_sel = lane >> 3;
    const int b_roff = ((b_sel & 2) ? 8 : 0) + b_g;
    const int b_lo  = b_sel & 1;

    uint32_t a_row[4], b_row[2];
#pragma unroll
    for (int mf = 0; mf < 4; mf++)
        a_row[mf] = (uint32_t)((warprow * 64 + mf * 16 + a_r) * ROWB);
#pragma unroll
    for (int nh = 0; nh < 2; nh++)
        b_row[nh] = (uint32_t)(A_REGION + (warpcol * 32 + nh * 16 + b_roff) * ROWB);
    uint32_t a_xk[4], b_xk[4];
#pragma unroll
    for (int kk = 0; kk < 4; kk++) {
        a_xk[kk] = (uint32_t)(((kk * 2 + a_hi) ^ a_m) << 4);
        b_xk[kk] = (uint32_t)(((kk * 2 + b_lo) ^ b_g) << 4);
    }

    load_stage(0, 0);
    asm volatile("cp.async.commit_group;\n");
    load_stage(1, 1);
    asm volatile("cp.async.commit_group;\n");

#pragma unroll
    for (int kt = 0; kt < NKIT_I8; kt++) {
        if (kt < NKIT_I8 - 1) {
            asm volatile("cp.async.wait_group %0;\n" ::"n"(1));
        } else {
            asm volatile("cp.async.wait_group %0;\n" ::"n"(0));
        }
        __syncthreads();
        if (kt + 2 < NKIT_I8) {
            load_stage(kt + 2, (kt + 2) % 3);
            asm volatile("cp.async.commit_group;\n");
        }

        const uint32_t sS = dbase + (kt % 3) * STG_BYTES;

#pragma unroll
        for (int kk = 0; kk < 4; kk++) {
            uint32_t a_reg[4][4];
            uint32_t b_reg[2][4];
#pragma unroll
            for (int mf = 0; mf < 4; mf++) {
                asm volatile(
                    "ldmatrix.sync.aligned.m8n8.x4.shared.b16 {%0,%1,%2,%3}, [%4];\n"
                    : "=r"(a_reg[mf][0]), "=r"(a_reg[mf][1]),
                      "=r"(a_reg[mf][2]), "=r"(a_reg[mf][3])
                    : "r"(sS + a_row[mf] + a_xk[kk]));
            }
#pragma unroll
            for (int nh = 0; nh < 2; nh++) {
                asm volatile(
                    "ldmatrix.sync.aligned.m8n8.x4.shared.b16 {%0,%1,%2,%3}, [%4];\n"
                    : "=r"(b_reg[nh][0]), "=r"(b_reg[nh][1]),
                      "=r"(b_reg[nh][2]), "=r"(b_reg[nh][3])
                    : "r"(sS + b_row[nh] + b_xk[kk]));
            }
#pragma unroll
            for (int mf = 0; mf < 4; mf++)
#pragma unroll
                for (int nf = 0; nf < 4; nf++) {
                    const uint32_t* b2p = &b_reg[nf >> 1][(nf & 1) * 2];
                    asm volatile(
                        "mma.sync.aligned.m16n8k32.row.col.s32.s8.s8.s32 "
                        "{%0,%1,%2,%3}, {%4,%5,%6,%7}, {%8,%9}, {%0,%1,%2,%3};\n"
                        : "+r"(acc[mf * 4 + nf][0]), "+r"(acc[mf * 4 + nf][1]),
                          "+r"(acc[mf * 4 + nf][2]), "+r"(acc[mf * 4 + nf][3])
                        : "r"(a_reg[mf][0]), "r"(a_reg[mf][1]),
                          "r"(a_reg[mf][2]), "r"(a_reg[mf][3]),
                          "r"(b2p[0]), "r"(b2p[1]));
                }
        }
    }
    __syncthreads();

    // Branchless float epilogue: score = ||e||^2 - (2*invx*inve)*acc.
#pragma unroll
    for (int mf = 0; mf < 4; mf++) {
        int r0 = warprow * 64 + mf * 16 + (lane >> 2);
        float w0 = 2.f * s_invx[r0], w1 = 2.f * s_invx[r0 + 8];
        float s1a = FINF, s2a = FINF, s1b = FINF, s2b = FINF;
        int i1a = 0, i1b = 0;
#pragma unroll
        for (int nf = 0; nf < 4; nf++) {
            int kl = warpcol * 32 + nf * 8 + 2 * (lane & 3);
            int k = n0 + kl;
            float e0 = s_esq[kl], e1 = s_esq[kl + 1];
            float v0 = s_inve[kl], v1 = s_inve[kl + 1];
            fupd(s1a, i1a, s2a, fmaf(-w0 * v0, (float)acc[mf * 4 + nf][0], e0), k);
            fupd(s1a, i1a, s2a, fmaf(-w0 * v1, (float)acc[mf * 4 + nf][1], e1), k + 1);
            fupd(s1b, i1b, s2b, fmaf(-w1 * v0, (float)acc[mf * 4 + nf][2], e0), k);
            fupd(s1b, i1b, s2b, fmaf(-w1 * v1, (float)acc[mf * 4 + nf][3], e1), k + 1);
        }
#pragma unroll
        for (int o = 1; o < 4; o <<= 1) {
            fmerge(s1a, i1a, s2a, o);
            fmerge(s1b, i1b, s2b, o);
        }
        if ((lane & 3) == 0) {
            epi_commit(sb1, sb2, r0, s1a, i1a, s2a);
            epi_commit(sb1, sb2, r0 + 8, s1b, i1b, s2b);
        }
    }
    __syncthreads();
    // Persist chunk-local minima (chunk-major, coalesced). NO global atomics.
    for (int i = tid; i < BM; i += 256) {
        g_blk1[(size_t)blockIdx.x * NTOK + row0 + i] = sb1[i];
        g_blk2[(size_t)blockIdx.x * NTOK + row0 + i] = sb2[i];
    }
}

// ---------------------------------------------------------------------------
// Cross-chunk reduction + flagging. One thread per row scans its 64 chunk
// minima (column-major = coalesced), computes global (min1, min2), writes
// g_best for certified rows, flags uncertain rows for exact resolution.
__global__ void k_select1() {
    int row = blockIdx.x * blockDim.x + threadIdx.x;
    if (row >= NTOK) return;
    unsigned long long b1 = 0xFFFFFFFFFFFFFFFFULL;
    unsigned b2 = 0xFFFFFFFFu;
#pragma unroll 4
    for (int c = 0; c < NCHK; c++) {
        unsigned long long c1 = g_blk1[(size_t)c * NTOK + row];
        unsigned c2 = g_blk2[(size_t)c * NTOK + row];
        unsigned long long mx = (b1 > c1) ? b1 : c1;
        b1 = (b1 < c1) ? b1 : c1;
        b2 = min(min(b2, c2), (unsigned)(mx >> 32));
    }
    float s1 = unmap_score((unsigned)(b1 >> 32));
    float s2 = unmap_score(b2);
    if (s2 - s1 < MARGIN1) {
        int p = atomicAdd(&g_nfall, 1);
        g_fall[p] = row;
        g_thr[row] = s1 + MARGIN1;
        g_best[row] = 0xFFFFFFFFFFFFFFFFULL;
    } else {
        g_best[row] = b1;
    }
}

// ---------------------------------------------------------------------------
// Candidate-based exact fp32 resolution (r15-proven). One CTA per flagged row.
__global__ __launch_bounds__(128) void k_exact(const float* __restrict__ E,
                                               const float* __restrict__ x) {
    __shared__ __align__(16) float xs[DIM];
    __shared__ int dir[NCHK];
    __shared__ int deep[NCHK];
    __shared__ int nd, nz;
    __shared__ unsigned long long best;

    const int tid = threadIdx.x;
    const int wid = tid >> 5;
    const int lane = tid & 31;
    const int n = g_nfall;

    for (int r = blockIdx.x; r < n; r += gridDim.x) {
        const int row = g_fall[r];
        if (tid == 0) { nd = 0; nz = 0; best = 0xFFFFFFFFFFFFFFFFULL; }
        __syncthreads();
        const float T = g_thr[row];
        {
            int b = row / TT, t = row % TT;
            for (int d = tid; d < DIM; d += 128)
                xs[d] = x[((size_t)b * DIM + d) * TT + t];
        }
        if (tid < NCHK) {
            unsigned long long m1 = g_blk1[(size_t)tid * NTOK + row];
            float c1 = unmap_score((unsigned)(m1 >> 32));
            float c2 = unmap_score(g_blk2[(size_t)tid * NTOK + row]);
            if (c2 <= T)       deep[atomicAdd(&nz, 1)] = tid;
            else if (c1 <= T)  dir[atomicAdd(&nd, 1)] = (int)(m1 & 0xFFFFFFFFu);
        }
        __syncthreads();

        for (int j = wid; j < nd; j += 4) {
            int k = dir[j];
            const float4* e4 = reinterpret_cast<const float4*>(E + (size_t)k * DIM);
            const float4* x4 = reinterpret_cast<const float4*>(xs);
            float s = 0.f;
#pragma unroll
            for (int i = 0; i < 4; i++) {
                float4 ev = e4[lane + i * 32], xv = x4[lane + i * 32];
                s += ev.x * xv.x + ev.y * xv.y + ev.z * xv.z + ev.w * xv.w;
            }
#pragma unroll
            for (int o = 16; o; o >>= 1) s += __shfl_xor_sync(~0u, s, o);
            if (lane == 0)
                atomicMin(&best, pack_score(g_esq[k] - 2.f * s, k));
        }
        for (int z = 0; z < nz; z++) {
            int kbase = deep[z] * BN;
            for (int j = wid; j < BN; j += 4) {
                int k = kbase + j;
                const float4* e4 = reinterpret_cast<const float4*>(E + (size_t)k * DIM);
                const float4* x4 = reinterpret_cast<const float4*>(xs);
                float s = 0.f;
#pragma unroll
                for (int i = 0; i < 4; i++) {
                    float4 ev = e4[lane + i * 32], xv = x4[lane + i * 32];
                    s += ev.x * xv.x + ev.y * xv.y + ev.z * xv.z + ev.w * xv.w;
                }
#pragma unroll
                for (int o = 16; o; o >>= 1) s += __shfl_xor_sync(~0u, s, o);
                if (lane == 0)
                    atomicMin(&best, pack_score(g_esq[k] - 2.f * s, k));
            }
        }
        __syncthreads();
        if (tid == 0) atomicMin(&g_best[row], best);
        __syncthreads();
    }
}

// ---------------------------------------------------------------------------
// Gather quantized = E[idx], permute back to [B, D, T], fused loss accum.
__global__ void k_output(const float* __restrict__ E, const float* __restrict__ x,
                         float* __restrict__ out) {
    __shared__ float s[TT][68];
    __shared__ int sidx[TT];
    __shared__ float wred[8];
    int b  = blockIdx.y;
    int d0 = blockIdx.x * 64;
    int tid = threadIdx.x;
    if (tid < TT) sidx[tid] = (int)(g_best[(size_t)b * TT + tid] & 0xFFFFFFFFu);
    __syncthreads();
    for (int i = tid; i < TT * 16; i += 256) {
        int t = i >> 4, c = (i & 15) * 4;
        float4 v = *reinterpret_cast<const float4*>(
            E + (size_t)sidx[t] * DIM + d0 + c);
        s[t][c] = v.x; s[t][c + 1] = v.y; s[t][c + 2] = v.z; s[t][c + 3] = v.w;
    }
    __syncthreads();
    float fsum = 0.f;
    for (int i = tid; i < 64 * TT; i += 256) {
        int dd = i / TT, t = i % TT;
        float e = s[t][dd];
        size_t off = ((size_t)b * DIM + d0 + dd) * TT + t;
        float df = e - x[off];
        fsum += df * df;
        out[off] = e;
    }
#pragma unroll
    for (int o = 16; o; o >>= 1) fsum += __shfl_xor_sync(~0u, fsum, o);
    if ((tid & 31) == 0) wred[tid >> 5] = fsum;
    __syncthreads();
    if (tid == 0) {
        float t = 0.f;
#pragma unroll
        for (int i = 0; i < 8; i++) t += wred[i];
        atomicAdd(&g_loss_acc, (double)t);
    }
}

__global__ void k_finalize(float* out, int out_size) {
    if (out_size > NELEM)
        out[NELEM] = (float)(1.25 * g_loss_acc / (double)((size_t)NTOK * DIM));
}

// ---------------------------------------------------------------------------
extern "C" void kernel_launch(void* const* d_in, const int* in_sizes, int n_in,
                              void* d_out, int out_size) {
    const float* x = (const float*)d_in[0];
    const float* E = (const float*)d_in[1];
    float* out = (float*)d_out;

    static int configured = 0;
    if (!configured) {
        cudaFuncSetAttribute(k_gemm_i8,
                             cudaFuncAttributeMaxDynamicSharedMemorySize, DYN_SMEM);
        cudaFuncSetAttribute(k_prep_x,
                             cudaFuncAttributeMaxDynamicSharedMemorySize,
                             512 * 33 * (int)sizeof(float));
        configured = 1;
    }

    k_init<<<1, 32>>>();
    k_prep_x<<<dim3(TT / 32, BATCH), 256, 512 * 33 * sizeof(float)>>>(x);
    k_prep_e<<<KEMB / 8, 256>>>(E);
    k_gemm_i8<<<dim3(KEMB / BN, NTOK / BM), 256, DYN_SMEM>>>();
    k_select1<<<(NTOK + 255) / 256, 256>>>();
    k_exact<<<NEXACT_CTAS, 128>>>(E, x);
    k_output<<<dim3(DIM / 64, BATCH), 256>>>(E, x, out);
    k_finalize<<<1, 1>>>(out, out_size);
}